// round 3
// baseline (speedup 1.0000x reference)
#include <cuda_runtime.h>
#include <math.h>

#define T 8192
#define E 1024
#define H 64
#define SPLITS 8
#define SPLITW (T / SPLITS)   // 1024 keys per split
#define BR 64                 // query rows per block (== blockDim)
#define BC 32                 // key tile

// ---------------- device scratch (module-load allocated, allowed) ----------
__device__ float g_q[T * H];
__device__ float g_k[T * H];
__device__ float g_v[T * H];
__device__ float g_op[(size_t)SPLITS * T * H];   // 16 MB partial outputs
__device__ float g_m[SPLITS * T];
__device__ float g_l[SPLITS * T];

// ---------------- projection GEMM: out[t][h] = sum_e X[t][e] * W[h][e] -----
// grid (T/64, 3), 256 threads. BM=64, BN=64(=H full), BK=32.
__global__ void proj_kernel(const float* __restrict__ Xq,
                            const float* __restrict__ Xk,
                            const float* __restrict__ Xv,
                            const float* __restrict__ Wq,
                            const float* __restrict__ Wk,
                            const float* __restrict__ Wv) {
    const float* X; const float* W; float* O;
    if (blockIdx.y == 0)      { X = Xq; W = Wq; O = g_q; }
    else if (blockIdx.y == 1) { X = Xk; W = Wk; O = g_k; }
    else                      { X = Xv; W = Wv; O = g_v; }

    __shared__ __align__(16) float Xs[32][64];  // [k][row]
    __shared__ __align__(16) float Ws[32][64];  // [k][h]

    const int tid  = threadIdx.x;
    const int row0 = blockIdx.x * 64;
    const int rBase = (tid >> 4) << 2;   // 0..60
    const int cBase = (tid & 15) << 2;   // 0..60

    float acc[4][4] = {};

    for (int e0 = 0; e0 < E; e0 += 32) {
        #pragma unroll
        for (int p = 0; p < 2; ++p) {
            int i = tid + p * 256;          // 0..511
            int r = i >> 3;                 // 0..63
            int c = (i & 7) << 2;           // 0..28
            float4 xv = *(const float4*)&X[(size_t)(row0 + r) * E + e0 + c];
            Xs[c + 0][r] = xv.x; Xs[c + 1][r] = xv.y;
            Xs[c + 2][r] = xv.z; Xs[c + 3][r] = xv.w;
            float4 wv = *(const float4*)&W[(size_t)r * E + e0 + c];
            Ws[c + 0][r] = wv.x; Ws[c + 1][r] = wv.y;
            Ws[c + 2][r] = wv.z; Ws[c + 3][r] = wv.w;
        }
        __syncthreads();
        #pragma unroll
        for (int kk = 0; kk < 32; ++kk) {
            float4 a = *(const float4*)&Xs[kk][rBase];
            float4 b = *(const float4*)&Ws[kk][cBase];
            float av[4] = {a.x, a.y, a.z, a.w};
            float bv[4] = {b.x, b.y, b.z, b.w};
            #pragma unroll
            for (int i = 0; i < 4; ++i)
                #pragma unroll
                for (int j = 0; j < 4; ++j)
                    acc[i][j] += av[i] * bv[j];
        }
        __syncthreads();
    }
    #pragma unroll
    for (int i = 0; i < 4; ++i)
        #pragma unroll
        for (int j = 0; j < 4; ++j)
            O[(size_t)(row0 + rBase + i) * H + cBase + j] = acc[i][j];
}

// ---------------- flash attention, split-K, thread-per-query-row -----------
// grid (T/BR, SPLITS), 64 threads.
__global__ void __launch_bounds__(64) flash_kernel() {
    __shared__ __align__(16) float ks[BC][H];
    __shared__ __align__(16) float vs[BC][H];

    const int tid  = threadIdx.x;
    const int row  = blockIdx.x * BR + tid;
    const int sp   = blockIdx.y;
    const int kstart   = sp * SPLITW;
    const int splitEnd = kstart + SPLITW;
    const int blockKend = min(splitEnd, blockIdx.x * BR + BR); // max key+1 any row in block needs
    const int myKend    = min(splitEnd, row + 1);

    float q[H], o[H];
    #pragma unroll
    for (int e = 0; e < H; e += 4) {
        float4 t4 = *(const float4*)&g_q[(size_t)row * H + e];
        q[e] = t4.x; q[e + 1] = t4.y; q[e + 2] = t4.z; q[e + 3] = t4.w;
        o[e] = 0.f;  o[e + 1] = 0.f;  o[e + 2] = 0.f;  o[e + 3] = 0.f;
    }
    float m = -INFINITY, l = 0.f;

    for (int k0 = kstart; k0 < blockKend; k0 += BC) {
        // cooperative tile load: BC*H floats = 512 float4 each for K and V
        #pragma unroll
        for (int p = 0; p < 8; ++p) {
            int i = tid + p * 64;          // 0..511
            int r = i >> 4;                // 0..31
            int c = (i & 15) << 2;         // 0..60
            *(float4*)&ks[r][c] = *(const float4*)&g_k[(size_t)(k0 + r) * H + c];
            *(float4*)&vs[r][c] = *(const float4*)&g_v[(size_t)(k0 + r) * H + c];
        }
        __syncthreads();

        int jmax = myKend - k0;
        if (jmax > BC) jmax = BC;
        for (int j = 0; j < jmax; ++j) {
            float s0 = 0.f, s1 = 0.f, s2 = 0.f, s3 = 0.f;
            #pragma unroll
            for (int e = 0; e < H; e += 4) {
                float4 kv = *(const float4*)&ks[j][e];
                s0 += q[e] * kv.x;     s1 += q[e + 1] * kv.y;
                s2 += q[e + 2] * kv.z; s3 += q[e + 3] * kv.w;
            }
            float sc = (s0 + s1 + s2 + s3) * 0.125f;
            if (sc > m) {                    // lazy rescale, amortized O(log n)
                float corr = __expf(m - sc); // first hit: exp(-inf)=0
                m = sc;
                l *= corr;
                #pragma unroll
                for (int e = 0; e < H; ++e) o[e] *= corr;
            }
            float p = __expf(sc - m);
            l += p;
            #pragma unroll
            for (int e = 0; e < H; e += 4) {
                float4 vv = *(const float4*)&vs[j][e];
                o[e]     += p * vv.x; o[e + 1] += p * vv.y;
                o[e + 2] += p * vv.z; o[e + 3] += p * vv.w;
            }
        }
        __syncthreads();
    }

    const size_t base = (size_t)sp * T + row;
    g_m[base] = m;
    g_l[base] = l;
    #pragma unroll
    for (int e = 0; e < H; e += 4) {
        float4 t4 = make_float4(o[e], o[e + 1], o[e + 2], o[e + 3]);
        *(float4*)&g_op[base * H + e] = t4;
    }
}

// ---------------- combine split partials -----------------------------------
__global__ void combine_kernel(float* __restrict__ out) {
    int idx = blockIdx.x * blockDim.x + threadIdx.x;  // T*H threads
    int t = idx >> 6;
    int e = idx & 63;
    float mv[SPLITS];
    float M = -INFINITY;
    #pragma unroll
    for (int s = 0; s < SPLITS; ++s) {
        mv[s] = g_m[s * T + t];
        M = fmaxf(M, mv[s]);
    }
    float L = 0.f, acc = 0.f;
    #pragma unroll
    for (int s = 0; s < SPLITS; ++s) {
        float w = __expf(mv[s] - M);       // empty split: exp(-inf)=0
        L   += g_l[s * T + t] * w;
        acc += g_op[((size_t)s * T + t) * H + e] * w;
    }
    out[idx] = acc / L;
}

// ---------------- entry -----------------------------------------------------
extern "C" void kernel_launch(void* const* d_in, const int* in_sizes, int n_in,
                              void* d_out, int out_size) {
    const float* Xq = (const float*)d_in[0];
    const float* Xk = (const float*)d_in[1];
    const float* Xv = (const float*)d_in[2];
    // d_in[3] = mask: exactly causal triu(k=1); handled analytically, never read
    const float* Wq = (const float*)d_in[4];
    const float* Wk = (const float*)d_in[5];
    const float* Wv = (const float*)d_in[6];

    proj_kernel<<<dim3(T / 64, 3), 256>>>(Xq, Xk, Xv, Wq, Wk, Wv);
    flash_kernel<<<dim3(T / BR, SPLITS), 64>>>();
    combine_kernel<<<(T * H) / 256, 256>>>((float*)d_out);
}

// round 9
// speedup vs baseline: 1.6939x; 1.6939x over previous
#include <cuda_runtime.h>
#include <math.h>
#include <stdint.h>

#define T 8192
#define E 1024
#define H 64
#define SPLITS 4
#define SPLITW (T / SPLITS)   // 2048
#define QROWS 128
#define KTILE 64
#define NINF __int_as_float(0xff800000)

// ---------------- device scratch ----------------
__device__ float g_qh[T * H], g_ql[T * H];
__device__ float g_kh[T * H], g_kl[T * H];
__device__ float g_vth[H * T], g_vtl[H * T];     // V^T hi/lo
__device__ float g_op[(size_t)SPLITS * T * H];
__device__ float g_m[SPLITS * T], g_l[SPLITS * T];

// ---------------- helpers ----------------
__device__ __forceinline__ uint32_t tf32u(float x) {
    uint32_t u; asm("cvt.rna.tf32.f32 %0, %1;" : "=r"(u) : "f"(x)); return u;
}
__device__ __forceinline__ float tf32r(float x) { return __uint_as_float(tf32u(x)); }
__device__ __forceinline__ float ex2f(float x) {
    float r; asm("ex2.approx.f32 %0, %1;" : "=f"(r) : "f"(x)); return r;
}
// D += A*B, m16n8k8 tf32 (sm_80 baseline PTX -> legacy HMMA on sm_103)
__device__ __forceinline__ void mma8(float d[4], const uint32_t a[4], const uint32_t b[2]) {
    asm volatile("mma.sync.aligned.m16n8k8.row.col.f32.tf32.tf32.f32 "
                 "{%0,%1,%2,%3}, {%4,%5,%6,%7}, {%8,%9}, {%0,%1,%2,%3};"
                 : "+f"(d[0]), "+f"(d[1]), "+f"(d[2]), "+f"(d[3])
                 : "r"(a[0]), "r"(a[1]), "r"(a[2]), "r"(a[3]), "r"(b[0]), "r"(b[1]));
}

// ---------------- projection GEMM (tf32 mma, hi/lo compensated) -------------
// out[t][h] = sum_e X[t][e] * W[h][e].  CTA: 128 thr (4 warps x 32 rows), M=128.
#define PSX 36
__global__ void __launch_bounds__(128, 2) proj_mma(
    const float* __restrict__ Xq, const float* __restrict__ Xk, const float* __restrict__ Xv,
    const float* __restrict__ Wq, const float* __restrict__ Wk, const float* __restrict__ Wv) {
    extern __shared__ float sm[];
    float* Xh = sm;                   // 128 x 36
    float* Xl = Xh + 128 * PSX;
    float* Wh = Xl + 128 * PSX;       // 64 x 36
    float* Wl = Wh + 64 * PSX;

    const float* X; const float* W;
    if (blockIdx.y == 0)      { X = Xq; W = Wq; }
    else if (blockIdx.y == 1) { X = Xk; W = Wk; }
    else                      { X = Xv; W = Wv; }

    const int tid = threadIdx.x, lane = tid & 31, wid = tid >> 5;
    const int row0 = blockIdx.x * 128;
    const int g = lane >> 2, tg = lane & 3;

    float o[2][8][4] = {};

    for (int e0 = 0; e0 < E; e0 += 32) {
        {   // stage X tile: one row per thread
            const float* src = &X[(size_t)(row0 + tid) * E + e0];
            #pragma unroll
            for (int j = 0; j < 8; ++j) {
                float4 v = *(const float4*)&src[j * 4];
                float vs[4] = {v.x, v.y, v.z, v.w};
                #pragma unroll
                for (int q = 0; q < 4; ++q) {
                    float h = tf32r(vs[q]);
                    Xh[tid * PSX + j * 4 + q] = h;
                    Xl[tid * PSX + j * 4 + q] = tf32r(vs[q] - h);
                }
            }
            int wr = tid >> 1, wc = (tid & 1) * 16;
            const float* wsrc = &W[(size_t)wr * E + e0 + wc];
            #pragma unroll
            for (int j = 0; j < 4; ++j) {
                float4 v = *(const float4*)&wsrc[j * 4];
                float vs[4] = {v.x, v.y, v.z, v.w};
                #pragma unroll
                for (int q = 0; q < 4; ++q) {
                    float h = tf32r(vs[q]);
                    Wh[wr * PSX + wc + j * 4 + q] = h;
                    Wl[wr * PSX + wc + j * 4 + q] = tf32r(vs[q] - h);
                }
            }
        }
        __syncthreads();

        #pragma unroll
        for (int kc = 0; kc < 4; ++kc) {
            uint32_t ah[2][4], al[2][4];
            #pragma unroll
            for (int mt = 0; mt < 2; ++mt) {
                int r = wid * 32 + mt * 16 + g;
                int c = kc * 8 + tg;
                ah[mt][0] = __float_as_uint(Xh[r * PSX + c]);
                ah[mt][1] = __float_as_uint(Xh[(r + 8) * PSX + c]);
                ah[mt][2] = __float_as_uint(Xh[r * PSX + c + 4]);
                ah[mt][3] = __float_as_uint(Xh[(r + 8) * PSX + c + 4]);
                al[mt][0] = __float_as_uint(Xl[r * PSX + c]);
                al[mt][1] = __float_as_uint(Xl[(r + 8) * PSX + c]);
                al[mt][2] = __float_as_uint(Xl[r * PSX + c + 4]);
                al[mt][3] = __float_as_uint(Xl[(r + 8) * PSX + c + 4]);
            }
            #pragma unroll
            for (int nf = 0; nf < 8; ++nf) {
                int hrow = nf * 8 + g;
                int c = kc * 8 + tg;
                uint32_t bh[2] = { __float_as_uint(Wh[hrow * PSX + c]),
                                   __float_as_uint(Wh[hrow * PSX + c + 4]) };
                uint32_t bl[2] = { __float_as_uint(Wl[hrow * PSX + c]),
                                   __float_as_uint(Wl[hrow * PSX + c + 4]) };
                #pragma unroll
                for (int mt = 0; mt < 2; ++mt) {
                    mma8(o[mt][nf], ah[mt], bh);
                    mma8(o[mt][nf], al[mt], bh);
                    mma8(o[mt][nf], ah[mt], bl);
                }
            }
        }
        __syncthreads();
    }

    // epilogue: hi/lo split, scattered stores
    #pragma unroll
    for (int mt = 0; mt < 2; ++mt) {
        #pragma unroll
        for (int nf = 0; nf < 8; ++nf) {
            #pragma unroll
            for (int c = 0; c < 4; ++c) {
                int r   = row0 + wid * 32 + mt * 16 + g + ((c >= 2) ? 8 : 0);
                int col = nf * 8 + 2 * tg + (c & 1);
                float v = o[mt][nf][c];
                float vh = tf32r(v), vl = tf32r(v - vh);
                if (blockIdx.y == 0) {
                    g_qh[(size_t)r * H + col] = vh; g_ql[(size_t)r * H + col] = vl;
                } else if (blockIdx.y == 1) {
                    g_kh[(size_t)r * H + col] = vh; g_kl[(size_t)r * H + col] = vl;
                } else {
                    g_vth[(size_t)col * T + r] = vh; g_vtl[(size_t)col * T + r] = vl;
                }
            }
        }
    }
}

// ---------------- flash attention, split-K, mma.sync tf32 -------------------
// CTA: 256 thr = 8 warps x 16 query rows = 128 rows. 64-key tiles.
#define SKV 68    // padded stride (floats) for K/V/P smem tiles
__global__ void __launch_bounds__(256, 1) flash_mma() {
    extern __shared__ float sm[];
    float* KH  = sm;                    // 64 x 68
    float* KL  = KH  + 64 * SKV;
    float* VTH = KL  + 64 * SKV;        // 64 x 68 (h-major)
    float* VTL = VTH + 64 * SKV;
    float* P   = VTL + 64 * SKV;        // 128 x 68

    const int tid = threadIdx.x, lane = tid & 31, wid = tid >> 5;
    const int g = lane >> 2, tg = lane & 3;
    const int rb = blockIdx.x, sp = blockIdx.y;
    const int wr0 = rb * QROWS + wid * 16;        // warp's first query row
    const int kstart = sp * SPLITW;
    const int kend   = min(kstart + SPLITW, rb * QROWS + QROWS);
    const int ntiles = (kend > kstart) ? (kend - kstart) / KTILE : 0;
    const float CSC = 0.18033688011112042f;       // 0.125 * log2(e)

    if (ntiles == 0) {   // split entirely above this block's rows
        int r = rb * QROWS + (tid >> 1);
        size_t base = ((size_t)sp * T + r) * H + (tid & 1) * 32;
        float4 z = make_float4(0.f, 0.f, 0.f, 0.f);
        #pragma unroll
        for (int c = 0; c < 32; c += 4) *(float4*)&g_op[base + c] = z;
        if (tid < QROWS) {
            g_m[sp * T + rb * QROWS + tid] = -1.25e29f;
            g_l[sp * T + rb * QROWS + tid] = 0.f;
        }
        return;
    }

    // persistent Q fragments (hi/lo), loaded straight from gmem
    uint32_t Qh[8][4], Ql[8][4];
    {
        const int r = wr0 + g;
        #pragma unroll
        for (int kc = 0; kc < 8; ++kc) {
            int c = kc * 8 + tg;
            Qh[kc][0] = __float_as_uint(g_qh[(size_t)r * H + c]);
            Qh[kc][1] = __float_as_uint(g_qh[(size_t)(r + 8) * H + c]);
            Qh[kc][2] = __float_as_uint(g_qh[(size_t)r * H + c + 4]);
            Qh[kc][3] = __float_as_uint(g_qh[(size_t)(r + 8) * H + c + 4]);
            Ql[kc][0] = __float_as_uint(g_ql[(size_t)r * H + c]);
            Ql[kc][1] = __float_as_uint(g_ql[(size_t)(r + 8) * H + c]);
            Ql[kc][2] = __float_as_uint(g_ql[(size_t)r * H + c + 4]);
            Ql[kc][3] = __float_as_uint(g_ql[(size_t)(r + 8) * H + c + 4]);
        }
    }

    float o[8][4] = {};
    float mA = -1e30f, mB = -1e30f, lA = 0.f, lB = 0.f;

    for (int it = 0; it < ntiles; ++it) {
        const int k0 = kstart + it * KTILE;
        {   // stage K(hi,lo) and V^T(hi,lo) tiles
            int rr = tid >> 2, cs = (tid & 3) * 16;
            const float* kh = &g_kh[(size_t)(k0 + rr) * H + cs];
            const float* kl = &g_kl[(size_t)(k0 + rr) * H + cs];
            const float* vh = &g_vth[(size_t)rr * T + k0 + cs];
            const float* vl = &g_vtl[(size_t)rr * T + k0 + cs];
            #pragma unroll
            for (int j = 0; j < 4; ++j) {
                float4 a = *(const float4*)&kh[j * 4];
                float4 b = *(const float4*)&kl[j * 4];
                float4 cvh = *(const float4*)&vh[j * 4];
                float4 cvl = *(const float4*)&vl[j * 4];
                *(float4*)&KH [rr * SKV + cs + j * 4] = a;
                *(float4*)&KL [rr * SKV + cs + j * 4] = b;
                *(float4*)&VTH[rr * SKV + cs + j * 4] = cvh;
                *(float4*)&VTL[rr * SKV + cs + j * 4] = cvl;
            }
        }
        __syncthreads();

        if (k0 <= wr0 + 15) {   // warp has at least one causal-valid pair
            // ---- S = Q K^T (3-term hi/lo) ----
            float S[8][4] = {};
            #pragma unroll
            for (int kc = 0; kc < 8; ++kc) {
                int c = kc * 8 + tg;
                #pragma unroll
                for (int nf = 0; nf < 8; ++nf) {
                    int kr = nf * 8 + g;
                    uint32_t bh[2] = { __float_as_uint(KH[kr * SKV + c]),
                                       __float_as_uint(KH[kr * SKV + c + 4]) };
                    uint32_t bl[2] = { __float_as_uint(KL[kr * SKV + c]),
                                       __float_as_uint(KL[kr * SKV + c + 4]) };
                    mma8(S[nf], Qh[kc], bh);
                    mma8(S[nf], Ql[kc], bh);
                    mma8(S[nf], Qh[kc], bl);
                }
            }
            // ---- causal mask ----
            if (k0 + KTILE - 1 > wr0) {
                const int rA = wr0 + g, rBr = rA + 8;
                #pragma unroll
                for (int nf = 0; nf < 8; ++nf) {
                    int key = k0 + nf * 8 + 2 * tg;
                    if (key     > rA)  S[nf][0] = NINF;
                    if (key + 1 > rA)  S[nf][1] = NINF;
                    if (key     > rBr) S[nf][2] = NINF;
                    if (key + 1 > rBr) S[nf][3] = NINF;
                }
            }
            // ---- online softmax ----
            float tA = NINF, tB = NINF;
            #pragma unroll
            for (int nf = 0; nf < 8; ++nf) {
                tA = fmaxf(tA, fmaxf(S[nf][0], S[nf][1]));
                tB = fmaxf(tB, fmaxf(S[nf][2], S[nf][3]));
            }
            tA = fmaxf(tA, __shfl_xor_sync(0xffffffffu, tA, 1));
            tA = fmaxf(tA, __shfl_xor_sync(0xffffffffu, tA, 2));
            tB = fmaxf(tB, __shfl_xor_sync(0xffffffffu, tB, 1));
            tB = fmaxf(tB, __shfl_xor_sync(0xffffffffu, tB, 2));
            float nmA = fmaxf(mA, tA), nmB = fmaxf(mB, tB);
            float cA = (nmA > mA) ? ex2f((mA - nmA) * CSC) : 1.f;
            float cB = (nmB > mB) ? ex2f((mB - nmB) * CSC) : 1.f;
            mA = nmA; mB = nmB;
            lA *= cA;  lB *= cB;
            #pragma unroll
            for (int nf = 0; nf < 8; ++nf) {
                o[nf][0] *= cA; o[nf][1] *= cA;
                o[nf][2] *= cB; o[nf][3] *= cB;
            }
            // ---- P = exp2((S - m)*CSC), tf32-rounded, to per-warp smem ----
            float* Pw = P + (wid * 16 + g) * SKV;
            #pragma unroll
            for (int nf = 0; nf < 8; ++nf) {
                uint32_t u0 = tf32u(ex2f((S[nf][0] - mA) * CSC));
                uint32_t u1 = tf32u(ex2f((S[nf][1] - mA) * CSC));
                uint32_t u2 = tf32u(ex2f((S[nf][2] - mB) * CSC));
                uint32_t u3 = tf32u(ex2f((S[nf][3] - mB) * CSC));
                lA += __uint_as_float(u0) + __uint_as_float(u1);
                lB += __uint_as_float(u2) + __uint_as_float(u3);
                int col = nf * 8 + 2 * tg;
                *(float2*)&Pw[col]           = make_float2(__uint_as_float(u0), __uint_as_float(u1));
                *(float2*)&Pw[8 * SKV + col] = make_float2(__uint_as_float(u2), __uint_as_float(u3));
            }
            __syncwarp();
            // ---- O += P V  (V hi/lo) ----
            #pragma unroll
            for (int kc = 0; kc < 8; ++kc) {
                int c = kc * 8 + tg;
                uint32_t pa[4];
                const float* Pb = P + wid * 16 * SKV;
                pa[0] = __float_as_uint(Pb[(g)     * SKV + c]);
                pa[1] = __float_as_uint(Pb[(g + 8) * SKV + c]);
                pa[2] = __float_as_uint(Pb[(g)     * SKV + c + 4]);
                pa[3] = __float_as_uint(Pb[(g + 8) * SKV + c + 4]);
                #pragma unroll
                for (int nf = 0; nf < 8; ++nf) {
                    int hr = nf * 8 + g;
                    uint32_t bh[2] = { __float_as_uint(VTH[hr * SKV + c]),
                                       __float_as_uint(VTH[hr * SKV + c + 4]) };
                    uint32_t bl[2] = { __float_as_uint(VTL[hr * SKV + c]),
                                       __float_as_uint(VTL[hr * SKV + c + 4]) };
                    mma8(o[nf], pa, bh);
                    mma8(o[nf], pa, bl);
                }
            }
        }
        __syncthreads();
    }

    // FIX (R7): each quad lane only holds 1/4 of the row's probability columns;
    // reduce the denominator partial sums across the quad before storing.
    lA += __shfl_xor_sync(0xffffffffu, lA, 1);
    lA += __shfl_xor_sync(0xffffffffu, lA, 2);
    lB += __shfl_xor_sync(0xffffffffu, lB, 1);
    lB += __shfl_xor_sync(0xffffffffu, lB, 2);

    // epilogue: split-K partials
    {
        const int rA = wr0 + g, rBr = rA + 8;
        const size_t bA = ((size_t)sp * T + rA) * H;
        const size_t bB = ((size_t)sp * T + rBr) * H;
        #pragma unroll
        for (int nf = 0; nf < 8; ++nf) {
            int col = nf * 8 + 2 * tg;
            *(float2*)&g_op[bA + col] = make_float2(o[nf][0], o[nf][1]);
            *(float2*)&g_op[bB + col] = make_float2(o[nf][2], o[nf][3]);
        }
        if (tg == 0) {
            g_m[sp * T + rA]  = 0.125f * mA;  g_l[sp * T + rA]  = lA;
            g_m[sp * T + rBr] = 0.125f * mB;  g_l[sp * T + rBr] = lB;
        }
    }
}

// ---------------- combine split partials -----------------------------------
__global__ void combine_kernel(float* __restrict__ out) {
    int idx = blockIdx.x * blockDim.x + threadIdx.x;
    int t = idx >> 6;
    int e = idx & 63;
    float mv[SPLITS];
    float M = -INFINITY;
    #pragma unroll
    for (int s = 0; s < SPLITS; ++s) {
        mv[s] = g_m[s * T + t];
        M = fmaxf(M, mv[s]);
    }
    float L = 0.f, acc = 0.f;
    #pragma unroll
    for (int s = 0; s < SPLITS; ++s) {
        float w = __expf(mv[s] - M);
        L   += g_l[s * T + t] * w;
        acc += g_op[((size_t)s * T + t) * H + e] * w;
    }
    out[idx] = acc / L;
}

// ---------------- entry -----------------------------------------------------
extern "C" void kernel_launch(void* const* d_in, const int* in_sizes, int n_in,
                              void* d_out, int out_size) {
    const float* Xq = (const float*)d_in[0];
    const float* Xk = (const float*)d_in[1];
    const float* Xv = (const float*)d_in[2];
    // d_in[3] = mask: exactly causal triu(k=1); handled analytically, never read
    const float* Wq = (const float*)d_in[4];
    const float* Wk = (const float*)d_in[5];
    const float* Wv = (const float*)d_in[6];

    const int proj_smem  = (2 * 128 * PSX + 2 * 64 * PSX) * 4;   // 55296 B
    const int flash_smem = (4 * 64 * SKV + 128 * SKV) * 4;       // 104448 B
    cudaFuncSetAttribute(proj_mma,  cudaFuncAttributeMaxDynamicSharedMemorySize, proj_smem);
    cudaFuncSetAttribute(flash_mma, cudaFuncAttributeMaxDynamicSharedMemorySize, flash_smem);

    proj_mma<<<dim3(T / 128, 3), 128, proj_smem>>>(Xq, Xk, Xv, Wq, Wk, Wv);
    flash_mma<<<dim3(T / QROWS, SPLITS), 256, flash_smem>>>();
    combine_kernel<<<(T * H) / 256, 256>>>((float*)d_out);
}